// round 6
// baseline (speedup 1.0000x reference)
#include <cuda_runtime.h>

#define NB 1024    // batch rows
#define NL 512     // labels per row
#define NT 256     // threads per block
#define NW 8       // warps per block (one row per warp)
#define NBLK (NB/NW)   // 128 blocks
#define KB 512     // histogram bins
#define BPL (KB/32)    // bins per lane = 16
#define LOV (-8.0f)
#define BW  (0.03125f)   // 1/32
#define INVW (32.0f)
#define FULL 0xffffffffu

__device__ float g_row[NB];
__device__ int   g_cnt = 0;   // self-resetting across graph replays

__inline__ __device__ float warpSum(float v) {
#pragma unroll
    for (int o = 16; o; o >>= 1) v += __shfl_xor_sync(FULL, v, o);
    return v;
}

__global__ __launch_bounds__(NT) void row_kernel(const float* __restrict__ outp,
                                                 const int* __restrict__ tgt,
                                                 float* __restrict__ out) {
    // per-warp state; hist is later reused (aliased) as the float prefix-count array
    __shared__ __align__(16) int   hist[NW][KB];
    __shared__ __align__(16) float wpre[NW][KB];

    const int tid  = threadIdx.x;
    const int lane = tid & 31;
    const int wid  = tid >> 5;
    const int row  = blockIdx.x * NW + wid;

    int*   h  = hist[wid];
    float* hc = reinterpret_cast<float*>(h);   // aliased prefix counts
    float* hw = wpre[wid];

    // ---- zero own histogram (lane-private 16 bins, 4 x STS.128) ----
    {
        int4 z = make_int4(0, 0, 0, 0);
        int4* h4 = reinterpret_cast<int4*>(h);
#pragma unroll
        for (int u = 0; u < 4; u++) h4[lane * 4 + u] = z;
    }
    __syncwarp();

    // ---- load row (16 elems/lane, coalesced float4/int4), calib sums, histogram ----
    const float4* o4 = reinterpret_cast<const float4*>(outp + row * NL);
    const int4*   t4 = reinterpret_cast<const int4*>(tgt  + row * NL);
    float vv[16];
    unsigned negmask = 0;
    float pos_sum = 0.f, neg_sum = 0.f;
#pragma unroll
    for (int u = 0; u < 4; u++) {
        float4 ov = o4[lane + 32 * u];
        int4   tv = t4[lane + 32 * u];
        float* vp = &vv[u * 4];
        vp[0] = ov.x; vp[1] = ov.y; vp[2] = ov.z; vp[3] = ov.w;
        int tt[4] = {tv.x, tv.y, tv.z, tv.w};
#pragma unroll
        for (int k = 0; k < 4; k++) {
            float v = vp[k];
            if (tt[k] != 0) {
                pos_sum += fmaxf(1.f - v, 0.f);
                int b = __float2int_rd((v - LOV) * INVW);
                b = min(max(b, 0), KB - 1);
                atomicAdd(&h[b], 1);
            } else {
                neg_sum += fmaxf(1.f + v, 0.f);
                negmask |= 1u << (u * 4 + k);
            }
        }
    }
    __syncwarp();

    // ---- warp scan: lane owns bins [lane*16, lane*16+16) ----
    int c[BPL];
    {
        int4* h4 = reinterpret_cast<int4*>(h);
#pragma unroll
        for (int u = 0; u < 4; u++) {
            int4 q = h4[lane * 4 + u];
            c[u*4+0] = q.x; c[u*4+1] = q.y; c[u*4+2] = q.z; c[u*4+3] = q.w;
        }
    }
    const float ctr0 = LOV + ((float)(lane * BPL) + 0.5f) * BW;
    float rc = 0.f, rw = 0.f;
#pragma unroll
    for (int i = 0; i < BPL; i++) {
        float f = (float)c[i];
        rc += f;
        rw = fmaf(f, ctr0 + (float)i * BW, rw);
    }
    // inclusive warp scan of per-lane totals
    float sc = rc, sw = rw;
#pragma unroll
    for (int o = 1; o < 32; o <<= 1) {
        float tc = __shfl_up_sync(FULL, sc, o);
        float tw = __shfl_up_sync(FULL, sw, o);
        if (lane >= o) { sc += tc; sw += tw; }
    }
    const float n_pf = __shfl_sync(FULL, sc, 31);   // total positives (exact in fp32)
    float ac = sc - rc, aw = sw - rw;               // exclusive prefix for this lane
    __syncwarp();                                   // all reads of h done before overwrite
#pragma unroll
    for (int i = 0; i < BPL; i++) {
        float f = (float)c[i];
        ac += f;
        aw = fmaf(f, ctr0 + (float)i * BW, aw);
        hc[lane * BPL + i] = ac;
        hw[lane * BPL + i] = aw;
    }
    __syncwarp();

    // ---- per-negative O(1) lookup: sum relu(cc - p) ~= cc*cntBelow - wsumBelow ----
    float hacc = 0.f;
#pragma unroll
    for (int k = 0; k < 16; k++) {
        if (negmask & (1u << k)) {
            float cc = 1.f + vv[k];
            int m = (int)floorf((cc - LOV) * INVW - 0.5f) + 1;  // bins with center < cc
            m = min(max(m, 0), KB);
            if (m > 0) hacc = fmaf(cc, hc[m - 1], hacc - hw[m - 1]);
        }
    }

    // ---- warp reduce + per-row result ----
    float r0 = warpSum(hacc);
    float r1 = warpSum(pos_sum);
    float r2 = warpSum(neg_sum);

    int lastFlag = 0;
    if (lane == 0) {
        int n_p = (int)n_pf;
        int n_n = NL - n_p;
        float pos_calib = (n_p > 0) ? r1 / (float)n_p : 0.f;
        float neg_calib = (n_n > 0) ? r2 / (float)n_n : 0.f;
        long long denom = (long long)n_p * (long long)n_n;
        float hinge;
        if (denom > 0)      hinge = r0 / (float)denom;
        else if (n_p > 0)   hinge = pos_calib;
        else if (n_n > 0)   hinge = neg_calib;
        else                hinge = 1.f;
        g_row[row] = hinge + neg_calib + pos_calib;
        __threadfence();
        int old = atomicAdd(&g_cnt, 1);
        lastFlag = (old == NB - 1);
    }

    // ---- last finished warp computes the deterministic final mean ----
    if (__shfl_sync(FULL, lastFlag, 0)) {
        __threadfence();   // acquire all g_row writes
        float v = 0.f;
#pragma unroll
        for (int i = 0; i < NB / 32; i++) v += g_row[lane + 32 * i];
        v = warpSum(v);
        if (lane == 0) {
            out[0] = v / (float)NB;
            g_cnt = 0;     // reset for next graph replay
        }
    }
}

extern "C" void kernel_launch(void* const* d_in, const int* in_sizes, int n_in,
                              void* d_out, int out_size) {
    const float* outputs = (const float*)d_in[0];
    const int*   targets = (const int*)d_in[1];
    row_kernel<<<NBLK, NT>>>(outputs, targets, (float*)d_out);
}

// round 7
// speedup vs baseline: 1.1951x; 1.1951x over previous
#include <cuda_runtime.h>

#define NB 1024    // batch rows
#define NL 512     // labels per row
#define NT 128     // threads per block (one block per row)
#define NW 4       // warps per block
#define KB 512     // histogram bins
#define LOV (-8.0f)
#define BW  (0.03125f)   // 1/32
#define INVW (32.0f)
#define FULL 0xffffffffu

__device__ float g_row[NB];
__device__ int   g_cnt1[32];   // level-1 counters (32 blocks each)
__device__ int   g_cnt0 = 0;   // level-0 counter (32 slots)

__inline__ __device__ float warpSum(float v) {
#pragma unroll
    for (int o = 16; o; o >>= 1) v += __shfl_xor_sync(FULL, v, o);
    return v;
}

__global__ __launch_bounds__(NT) void row_kernel(const float* __restrict__ outp,
                                                 const int* __restrict__ tgt,
                                                 float* __restrict__ out) {
    __shared__ __align__(16) int    hcnt[KB];   // positive-count histogram
    __shared__ __align__(16) float2 SP[KB];     // inclusive prefix (count, wsum)
    __shared__ float wtc[NW], wtw[NW];
    __shared__ float s0[NW], s1[NW], s2[NW];
    __shared__ int amLast;

    const int row  = blockIdx.x;
    const int tid  = threadIdx.x;
    const int lane = tid & 31;
    const int wid  = tid >> 5;

    // ---- zero histogram (128 threads x int4 = 512 bins) ----
    reinterpret_cast<int4*>(hcnt)[tid] = make_int4(0, 0, 0, 0);
    __syncthreads();

    // ---- load row: ONE float4 + ONE int4 per thread (coalesced) ----
    const float4 ov = reinterpret_cast<const float4*>(outp + row * NL)[tid];
    const int4   tv = reinterpret_cast<const int4*>(tgt  + row * NL)[tid];
    float vv[4] = {ov.x, ov.y, ov.z, ov.w};
    int   tt[4] = {tv.x, tv.y, tv.z, tv.w};
    unsigned negmask = 0;
    float pos_sum = 0.f, neg_sum = 0.f;
#pragma unroll
    for (int k = 0; k < 4; k++) {
        float v = vv[k];
        if (tt[k] != 0) {
            pos_sum += fmaxf(1.f - v, 0.f);
            int b = __float2int_rd((v - LOV) * INVW);
            b = min(max(b, 0), KB - 1);
            atomicAdd(&hcnt[b], 1);
        } else {
            neg_sum += fmaxf(1.f + v, 0.f);
            negmask |= 1u << k;
        }
    }
    __syncthreads();

    // ---- scan: thread t owns bins 4t..4t+3 (count and count*center) ----
    int4 c4 = reinterpret_cast<const int4*>(hcnt)[tid];
    float ctr = LOV + ((float)(4 * tid) + 0.5f) * BW;
    float f0 = (float)c4.x, f1 = (float)c4.y, f2 = (float)c4.z, f3 = (float)c4.w;
    float w0 = f0 * ctr;
    float w1 = f1 * (ctr + BW);
    float w2 = f2 * (ctr + 2.f * BW);
    float w3 = f3 * (ctr + 3.f * BW);
    float ic1 = f0 + f1, ic2 = ic1 + f2, ic3 = ic2 + f3;
    float iw1 = w0 + w1, iw2 = iw1 + w2, iw3 = iw2 + w3;
    float sc = ic3, sw = iw3;
#pragma unroll
    for (int o = 1; o < 32; o <<= 1) {
        float tc = __shfl_up_sync(FULL, sc, o);
        float tw = __shfl_up_sync(FULL, sw, o);
        if (lane >= o) { sc += tc; sw += tw; }
    }
    if (lane == 31) { wtc[wid] = sc; wtw[wid] = sw; }
    __syncthreads();

    float offC = 0.f, offW = 0.f, n_pf = 0.f;
#pragma unroll
    for (int i = 0; i < NW; i++) {
        float a = wtc[i], b = wtw[i];
        n_pf += a;
        if (i < wid) { offC += a; offW += b; }
    }
    float exC = offC + sc - ic3;
    float exW = offW + sw - iw3;
    SP[4 * tid + 0] = make_float2(exC + f0,  exW + w0);
    SP[4 * tid + 1] = make_float2(exC + ic1, exW + iw1);
    SP[4 * tid + 2] = make_float2(exC + ic2, exW + iw2);
    SP[4 * tid + 3] = make_float2(exC + ic3, exW + iw3);
    __syncthreads();

    // ---- per-negative O(1) lookup: sum relu(cc - p) ~= cc*cntBelow - wsumBelow ----
    float hacc = 0.f;
#pragma unroll
    for (int k = 0; k < 4; k++) {
        if (negmask & (1u << k)) {
            float cc = 1.f + vv[k];
            int m = (int)floorf((cc - LOV) * INVW - 0.5f) + 1;  // bins w/ center < cc
            m = min(max(m, 0), KB);
            if (m > 0) {
                float2 pw = SP[m - 1];
                hacc = fmaf(cc, pw.x, hacc - pw.y);
            }
        }
    }

    // ---- block reduce ----
    float r0 = warpSum(hacc);
    float r1 = warpSum(pos_sum);
    float r2 = warpSum(neg_sum);
    if (lane == 0) { s0[wid] = r0; s1[wid] = r1; s2[wid] = r2; }
    __syncthreads();

    if (tid == 0) {
        float ps = 0.f, qs = 0.f, ns = 0.f;
#pragma unroll
        for (int w = 0; w < NW; w++) { ps += s0[w]; qs += s1[w]; ns += s2[w]; }
        int n_p = (int)n_pf;
        int n_n = NL - n_p;
        float pos_calib = (n_p > 0) ? qs / (float)n_p : 0.f;
        float neg_calib = (n_n > 0) ? ns / (float)n_n : 0.f;
        long long denom = (long long)n_p * (long long)n_n;
        float hinge;
        if (denom > 0)      hinge = ps / (float)denom;
        else if (n_p > 0)   hinge = pos_calib;
        else if (n_n > 0)   hinge = neg_calib;
        else                hinge = 1.f;
        g_row[row] = hinge + neg_calib + pos_calib;
        __threadfence();
        // 2-level completion counter: <=32-way contention per address
        amLast = 0;
        int slot = row & 31;
        if (atomicAdd(&g_cnt1[slot], 1) == 31) {          // last of this slot's 32 blocks
            if (atomicAdd(&g_cnt0, 1) == 31) amLast = 1;  // last slot overall
        }
    }
    __syncthreads();

    // ---- globally-last block: deterministic final mean; reset counters ----
    if (amLast) {
        __threadfence();   // acquire all g_row writes
        float v = 0.f;
#pragma unroll
        for (int i = 0; i < NB / NT; i++) v += g_row[tid + NT * i];
        v = warpSum(v);
        if (lane == 0) s0[wid] = v;
        __syncthreads();
        if (tid < 32) g_cnt1[tid] = 0;     // reset for next graph replay
        if (tid == 0) {
            float t = 0.f;
#pragma unroll
            for (int w = 0; w < NW; w++) t += s0[w];
            out[0] = t / (float)NB;
            g_cnt0 = 0;
        }
    }
}

extern "C" void kernel_launch(void* const* d_in, const int* in_sizes, int n_in,
                              void* d_out, int out_size) {
    const float* outputs = (const float*)d_in[0];
    const int*   targets = (const int*)d_in[1];
    row_kernel<<<NB, NT>>>(outputs, targets, (float*)d_out);
}

// round 8
// speedup vs baseline: 1.2035x; 1.0070x over previous
#include <cuda_runtime.h>

#define NB 1024    // batch rows
#define NL 512     // labels per row
#define NT 128     // threads per block (one block per row)
#define NW 4       // warps per block
#define KB 256     // histogram bins
#define LOV (-8.0f)
#define BW  (0.0625f)    // 1/16
#define INVW (16.0f)
#define FULL 0xffffffffu

__device__ float g_row[NB];
__device__ int   g_cnt1[32];   // level-1 counters (32 blocks each)
__device__ int   g_cnt0 = 0;   // level-0 counter (32 slots)

__inline__ __device__ float warpSum(float v) {
#pragma unroll
    for (int o = 16; o; o >>= 1) v += __shfl_xor_sync(FULL, v, o);
    return v;
}

__global__ __launch_bounds__(NT) void row_kernel(const float* __restrict__ outp,
                                                 const int* __restrict__ tgt,
                                                 float* __restrict__ out) {
    __shared__ __align__(16) int    hcnt[KB];   // positive-count histogram
    __shared__ __align__(16) float2 SP[KB];     // inclusive prefix (count, wsum)
    __shared__ float s0[NW], s1[NW], s2[NW];
    __shared__ float sNp;
    __shared__ int amLast;

    const int row  = blockIdx.x;
    const int tid  = threadIdx.x;
    const int lane = tid & 31;
    const int wid  = tid >> 5;

    // ---- issue global loads FIRST (latency hides behind zero + barrier) ----
    const float4 ov = reinterpret_cast<const float4*>(outp + row * NL)[tid];
    const int4   tv = reinterpret_cast<const int4*>(tgt  + row * NL)[tid];

    // ---- zero histogram (128 threads x int2 = 256 bins) ----
    reinterpret_cast<int2*>(hcnt)[tid] = make_int2(0, 0);
    __syncthreads();                                   // barrier 1

    // ---- classify, calib sums, histogram atomics ----
    float vv[4] = {ov.x, ov.y, ov.z, ov.w};
    int   tt[4] = {tv.x, tv.y, tv.z, tv.w};
    unsigned negmask = 0;
    float pos_sum = 0.f, neg_sum = 0.f;
#pragma unroll
    for (int k = 0; k < 4; k++) {
        float v = vv[k];
        if (tt[k] != 0) {
            pos_sum += fmaxf(1.f - v, 0.f);
            int b = __float2int_rd((v - LOV) * INVW);
            b = min(max(b, 0), KB - 1);
            atomicAdd(&hcnt[b], 1);
        } else {
            neg_sum += fmaxf(1.f + v, 0.f);
            negmask |= 1u << k;
        }
    }
    __syncthreads();                                   // barrier 2

    // ---- scan by warp 0 only: lane owns bins 8*lane..8*lane+7 ----
    if (wid == 0) {
        int4 a = reinterpret_cast<const int4*>(hcnt)[lane * 2];
        int4 b = reinterpret_cast<const int4*>(hcnt)[lane * 2 + 1];
        int cb[8] = {a.x, a.y, a.z, a.w, b.x, b.y, b.z, b.w};
        const float ctr0 = LOV + ((float)(lane * 8) + 0.5f) * BW;
        float rc = 0.f, rw = 0.f;
#pragma unroll
        for (int i = 0; i < 8; i++) {
            float f = (float)cb[i];
            rc += f;
            rw = fmaf(f, ctr0 + (float)i * BW, rw);
        }
        float sc = rc, sw = rw;                         // inclusive scan of lane totals
#pragma unroll
        for (int o = 1; o < 32; o <<= 1) {
            float tc = __shfl_up_sync(FULL, sc, o);
            float tw = __shfl_up_sync(FULL, sw, o);
            if (lane >= o) { sc += tc; sw += tw; }
        }
        float ac = sc - rc, aw = sw - rw;               // exclusive prefix
#pragma unroll
        for (int i = 0; i < 8; i++) {
            float f = (float)cb[i];
            ac += f;
            aw = fmaf(f, ctr0 + (float)i * BW, aw);
            SP[lane * 8 + i] = make_float2(ac, aw);
        }
        if (lane == 31) sNp = sc;                       // n_p (exact integer in fp32)
    }
    __syncthreads();                                   // barrier 3

    // ---- per-negative O(1) lookup: sum relu(cc - p) ~= cc*cntBelow - wsumBelow ----
    float hacc = 0.f;
#pragma unroll
    for (int k = 0; k < 4; k++) {
        if (negmask & (1u << k)) {
            float cc = 1.f + vv[k];
            int m = (int)floorf((cc - LOV) * INVW - 0.5f) + 1;  // bins w/ center < cc
            m = min(max(m, 0), KB);
            if (m > 0) {
                float2 pw = SP[m - 1];
                hacc = fmaf(cc, pw.x, hacc - pw.y);
            }
        }
    }

    // ---- block reduce ----
    float r0 = warpSum(hacc);
    float r1 = warpSum(pos_sum);
    float r2 = warpSum(neg_sum);
    if (lane == 0) { s0[wid] = r0; s1[wid] = r1; s2[wid] = r2; }
    __syncthreads();                                   // barrier 4

    if (tid == 0) {
        float ps = 0.f, qs = 0.f, ns = 0.f;
#pragma unroll
        for (int w = 0; w < NW; w++) { ps += s0[w]; qs += s1[w]; ns += s2[w]; }
        int n_p = (int)sNp;
        int n_n = NL - n_p;
        float pos_calib = (n_p > 0) ? qs / (float)n_p : 0.f;
        float neg_calib = (n_n > 0) ? ns / (float)n_n : 0.f;
        long long denom = (long long)n_p * (long long)n_n;
        float hinge;
        if (denom > 0)      hinge = ps / (float)denom;
        else if (n_p > 0)   hinge = pos_calib;
        else if (n_n > 0)   hinge = neg_calib;
        else                hinge = 1.f;
        g_row[row] = hinge + neg_calib + pos_calib;
        __threadfence();
        // 2-level completion counter: <=32-way contention per address
        amLast = 0;
        int slot = row & 31;
        if (atomicAdd(&g_cnt1[slot], 1) == 31) {
            if (atomicAdd(&g_cnt0, 1) == 31) amLast = 1;
        }
    }
    __syncthreads();

    // ---- globally-last block: deterministic final mean; reset counters ----
    if (amLast) {
        __threadfence();   // acquire all g_row writes
        float v = 0.f;
#pragma unroll
        for (int i = 0; i < NB / NT; i++) v += g_row[tid + NT * i];
        v = warpSum(v);
        if (lane == 0) s0[wid] = v;
        __syncthreads();
        if (tid < 32) g_cnt1[tid] = 0;     // reset for next graph replay
        if (tid == 0) {
            float t = 0.f;
#pragma unroll
            for (int w = 0; w < NW; w++) t += s0[w];
            out[0] = t / (float)NB;
            g_cnt0 = 0;
        }
    }
}

extern "C" void kernel_launch(void* const* d_in, const int* in_sizes, int n_in,
                              void* d_out, int out_size) {
    const float* outputs = (const float*)d_in[0];
    const int*   targets = (const int*)d_in[1];
    row_kernel<<<NB, NT>>>(outputs, targets, (float*)d_out);
}